// round 1
// baseline (speedup 1.0000x reference)
#include <cuda_runtime.h>
#include <cstdint>

#define CB 2
#define CS 2048
#define CD 1024
#define CH 16
#define CHD 64
#define CBH (CB*CH)          // 32 batch-heads
#define CM (CB*CS)           // 4096 rows
#define OUT_ELEMS (CB*CS*CD) // 4,194,304
#define ATTN_ELEMS ((size_t)CBH*CS*CS) // 134,217,728

// Scratch (cudaMalloc is forbidden; __device__ globals are the sanctioned path)
__device__ float g_q[CBH*CS*CHD];
__device__ float g_k[CBH*CS*CHD];
__device__ float g_v[CBH*CS*CHD];
__device__ float g_ctx[CBH*CS*CHD];
__device__ float g_attn_fb[(size_t)CBH*CS*CS];  // fallback if d_out holds only `out`
__device__ int   g_mask_mode;

#define NEG_INF __int_as_float(0xff800000)

// ---------------------------------------------------------------------------
// Mask dtype fingerprint: mask[0,0..] is guaranteed true (global tokens).
// bool/uint8 -> first word 0x01010101 ; int32 -> 0x00000001 ; float32 -> 0x3F800000
// ---------------------------------------------------------------------------
__global__ void detect_mask_kernel(const uint32_t* __restrict__ mask) {
    uint32_t w = mask[0];
    int mode = 0;
    if (w == 0x01010101u)      mode = 0;  // uint8 bool
    else if (w == 1u)          mode = 1;  // int32
    else if (w == 0x3F800000u) mode = 2;  // float32
    g_mask_mode = mode;
}

// ---------------------------------------------------------------------------
// Projection GEMM: C = A[4096x1024] @ W[1024x1024] + bias, scattered to
// dst layout [B,H,S,HD].  64x64 tile, BK=16, 256 threads, 4x4 per thread.
// ---------------------------------------------------------------------------
__global__ void __launch_bounds__(256) proj_kernel(
    const float* __restrict__ A, const float* __restrict__ W,
    const float* __restrict__ bias, float* __restrict__ dst)
{
    __shared__ float As[16][65];  // [k][m], padded
    __shared__ float Ws[16][64];  // [k][n]
    const int tid = threadIdx.x;
    const int tx = tid & 15, ty = tid >> 4;
    const int m0 = blockIdx.y * 64, n0 = blockIdx.x * 64;
    const int arow = tid >> 2, akq = (tid & 3) * 4;
    const int wrow = tid >> 4, wc  = (tid & 15) * 4;

    const float* Aptr = A + (size_t)(m0 + arow) * CD + akq;
    const float* Wptr = W + (size_t)wrow * CD + n0 + wc;

    float acc[4][4] = {};
    for (int k0 = 0; k0 < CD; k0 += 16) {
        float4 a = *(const float4*)(Aptr + k0);
        float4 w = *(const float4*)(Wptr + (size_t)k0 * CD);
        __syncthreads();
        As[akq+0][arow] = a.x; As[akq+1][arow] = a.y;
        As[akq+2][arow] = a.z; As[akq+3][arow] = a.w;
        *(float4*)&Ws[wrow][wc] = w;
        __syncthreads();
        #pragma unroll
        for (int k = 0; k < 16; ++k) {
            float ra[4], rb[4];
            #pragma unroll
            for (int i = 0; i < 4; ++i) ra[i] = As[k][ty*4+i];
            #pragma unroll
            for (int j = 0; j < 4; ++j) rb[j] = Ws[k][tx*4+j];
            #pragma unroll
            for (int i = 0; i < 4; ++i)
                #pragma unroll
                for (int j = 0; j < 4; ++j)
                    acc[i][j] = fmaf(ra[i], rb[j], acc[i][j]);
        }
    }
    #pragma unroll
    for (int i = 0; i < 4; ++i) {
        int m = m0 + ty*4 + i;
        int b = m >> 11, s = m & (CS-1);
        #pragma unroll
        for (int j = 0; j < 4; ++j) {
            int n = n0 + tx*4 + j;
            int h = n >> 6, hd = n & 63;
            dst[(((size_t)(b*CH + h)*CS) + s)*CHD + hd] = acc[i][j] + bias[n];
        }
    }
}

// ---------------------------------------------------------------------------
// Scores: S = scale * Q @ K^T per batch-head, masked -> raw scores buffer.
// K-dim is exactly 64 so each 64x64 tile needs ONE smem load of Q and K tiles.
// ---------------------------------------------------------------------------
__global__ void __launch_bounds__(256) qk_kernel(
    const void* __restrict__ maskp, float* __restrict__ scores)
{
    __shared__ float Qs[64][65];
    __shared__ float Ks[64][65];
    const int bh = blockIdx.z;
    const int q0 = blockIdx.y * 64, k0 = blockIdx.x * 64;
    const float* Qb = g_q + (size_t)bh * CS * CHD;
    const float* Kb = g_k + (size_t)bh * CS * CHD;
    const int tid = threadIdx.x, tx = tid & 15, ty = tid >> 4;
    const int lrow = tid >> 2, lc = tid & 3;

    #pragma unroll
    for (int i = 0; i < 4; ++i) {
        int col = lc * 16 + i * 4;
        float4 q4 = *(const float4*)(Qb + (size_t)(q0 + lrow) * CHD + col);
        float4 k4 = *(const float4*)(Kb + (size_t)(k0 + lrow) * CHD + col);
        Qs[lrow][col+0]=q4.x; Qs[lrow][col+1]=q4.y; Qs[lrow][col+2]=q4.z; Qs[lrow][col+3]=q4.w;
        Ks[lrow][col+0]=k4.x; Ks[lrow][col+1]=k4.y; Ks[lrow][col+2]=k4.z; Ks[lrow][col+3]=k4.w;
    }
    __syncthreads();

    float acc[4][4] = {};
    #pragma unroll 16
    for (int d = 0; d < 64; ++d) {
        float rq[4], rk[4];
        #pragma unroll
        for (int i = 0; i < 4; ++i) rq[i] = Qs[ty*4+i][d];
        #pragma unroll
        for (int j = 0; j < 4; ++j) rk[j] = Ks[tx*4+j][d];
        #pragma unroll
        for (int i = 0; i < 4; ++i)
            #pragma unroll
            for (int j = 0; j < 4; ++j)
                acc[i][j] = fmaf(rq[i], rk[j], acc[i][j]);
    }

    const int mode = g_mask_mode;
    const unsigned char* m8 = (const unsigned char*)maskp;
    const int*   m32 = (const int*)maskp;
    const float* mf  = (const float*)maskp;
    float* srow = scores + (size_t)bh * CS * CS;
    #pragma unroll
    for (int i = 0; i < 4; ++i) {
        int gq = q0 + ty*4 + i;
        #pragma unroll
        for (int j = 0; j < 4; ++j) {
            int gk = k0 + tx*4 + j;
            size_t midx = (size_t)gq * CS + gk;
            bool keep = (mode == 0) ? (m8[midx] != 0)
                      : (mode == 1) ? (m32[midx] != 0)
                                    : (mf[midx] != 0.0f);
            float v = acc[i][j] * 0.125f;   // 1/sqrt(64)
            srow[midx] = keep ? v : NEG_INF;
        }
    }
}

// ---------------------------------------------------------------------------
// Row softmax in-place over raw scores. One block per row; values stay in regs.
// ---------------------------------------------------------------------------
__global__ void __launch_bounds__(256) softmax_kernel(float* __restrict__ attn)
{
    float* p = attn + (size_t)blockIdx.x * CS;
    const int tid = threadIdx.x;
    float v[8];
    #pragma unroll
    for (int i = 0; i < 8; ++i) v[i] = p[tid + i*256];

    float m = v[0];
    #pragma unroll
    for (int i = 1; i < 8; ++i) m = fmaxf(m, v[i]);
    __shared__ float redm[8], reds[8];
    #pragma unroll
    for (int o = 16; o > 0; o >>= 1) m = fmaxf(m, __shfl_xor_sync(0xffffffffu, m, o));
    if ((tid & 31) == 0) redm[tid >> 5] = m;
    __syncthreads();
    m = redm[0];
    #pragma unroll
    for (int i = 1; i < 8; ++i) m = fmaxf(m, redm[i]);

    float s = 0.f;
    #pragma unroll
    for (int i = 0; i < 8; ++i) { v[i] = __expf(v[i] - m); s += v[i]; }
    #pragma unroll
    for (int o = 16; o > 0; o >>= 1) s += __shfl_xor_sync(0xffffffffu, s, o);
    if ((tid & 31) == 0) reds[tid >> 5] = s;
    __syncthreads();
    s = 0.f;
    #pragma unroll
    for (int i = 0; i < 8; ++i) s += reds[i];
    float inv = 1.0f / s;
    #pragma unroll
    for (int i = 0; i < 8; ++i) p[tid + i*256] = v[i] * inv;
}

// ---------------------------------------------------------------------------
// PV: ctx[bh] = attn[bh] (2048x2048) @ V[bh] (2048x64). BM=64, BN=64, BK=32.
// ---------------------------------------------------------------------------
__global__ void __launch_bounds__(256) pv_kernel(const float* __restrict__ attn)
{
    __shared__ float As[32][65];  // [k][m]
    __shared__ float Vs[32][64];  // [k][n]
    const int bh = blockIdx.y, m0 = blockIdx.x * 64;
    const float* Ab = attn + (size_t)bh * CS * CS;
    const float* Vb = g_v + (size_t)bh * CS * CHD;
    const int tid = threadIdx.x, tx = tid & 15, ty = tid >> 4;
    const int arow = tid >> 2, ac = tid & 3;   // A: 4 threads/row, 2 float4 each
    const int vrow = tid >> 3, vc = tid & 7;   // V: 8 threads/row, 2 float4 each

    float acc[4][4] = {};
    for (int kk0 = 0; kk0 < CS; kk0 += 32) {
        const float* arp = Ab + (size_t)(m0 + arow) * CS + kk0;
        float4 a0 = *(const float4*)(arp + ac*4);
        float4 a1 = *(const float4*)(arp + ac*4 + 16);
        const float* vrp = Vb + (size_t)(kk0 + vrow) * CHD;
        float4 v0 = *(const float4*)(vrp + vc*4);
        float4 v1 = *(const float4*)(vrp + vc*4 + 32);
        __syncthreads();
        As[ac*4+0][arow]=a0.x; As[ac*4+1][arow]=a0.y; As[ac*4+2][arow]=a0.z; As[ac*4+3][arow]=a0.w;
        As[ac*4+16][arow]=a1.x; As[ac*4+17][arow]=a1.y; As[ac*4+18][arow]=a1.z; As[ac*4+19][arow]=a1.w;
        *(float4*)&Vs[vrow][vc*4]      = v0;
        *(float4*)&Vs[vrow][vc*4 + 32] = v1;
        __syncthreads();
        #pragma unroll
        for (int k = 0; k < 32; ++k) {
            float ra[4], rb[4];
            #pragma unroll
            for (int i = 0; i < 4; ++i) ra[i] = As[k][ty*4+i];
            #pragma unroll
            for (int j = 0; j < 4; ++j) rb[j] = Vs[k][tx*4+j];
            #pragma unroll
            for (int i = 0; i < 4; ++i)
                #pragma unroll
                for (int j = 0; j < 4; ++j)
                    acc[i][j] = fmaf(ra[i], rb[j], acc[i][j]);
        }
    }
    #pragma unroll
    for (int i = 0; i < 4; ++i)
        #pragma unroll
        for (int j = 0; j < 4; ++j)
            g_ctx[(size_t)bh*CS*CHD + (size_t)(m0 + ty*4+i)*CHD + tx*4+j] = acc[i][j];
}

// ---------------------------------------------------------------------------
// Output projection: out = ctx(B,H,S,HD -> B,S,D gather) @ Wo + bo
// ---------------------------------------------------------------------------
__global__ void __launch_bounds__(256) outproj_kernel(
    const float* __restrict__ W, const float* __restrict__ bias, float* __restrict__ out)
{
    __shared__ float As[16][65];
    __shared__ float Ws[16][64];
    const int tid = threadIdx.x, tx = tid & 15, ty = tid >> 4;
    const int m0 = blockIdx.y * 64, n0 = blockIdx.x * 64;
    const int arow = tid >> 2, akq = (tid & 3) * 4;
    const int wrow = tid >> 4, wc  = (tid & 15) * 4;

    const int m = m0 + arow;
    const int b = m >> 11, s = m & (CS-1);
    const float* ctxb = g_ctx + ((size_t)b*CH*CS + s) * CHD;  // + h*CS*CHD + hd
    const float* Wptr = W + (size_t)wrow * CD + n0 + wc;

    float acc[4][4] = {};
    for (int k0 = 0; k0 < CD; k0 += 16) {
        int h = k0 >> 6;
        int hd0 = (k0 & 63) + akq;   // 16-chunks never straddle the 64 boundary
        float4 a = *(const float4*)(ctxb + (size_t)h*CS*CHD + hd0);
        float4 w = *(const float4*)(Wptr + (size_t)k0 * CD);
        __syncthreads();
        As[akq+0][arow] = a.x; As[akq+1][arow] = a.y;
        As[akq+2][arow] = a.z; As[akq+3][arow] = a.w;
        *(float4*)&Ws[wrow][wc] = w;
        __syncthreads();
        #pragma unroll
        for (int k = 0; k < 16; ++k) {
            float ra[4], rb[4];
            #pragma unroll
            for (int i = 0; i < 4; ++i) ra[i] = As[k][ty*4+i];
            #pragma unroll
            for (int j = 0; j < 4; ++j) rb[j] = Ws[k][tx*4+j];
            #pragma unroll
            for (int i = 0; i < 4; ++i)
                #pragma unroll
                for (int j = 0; j < 4; ++j)
                    acc[i][j] = fmaf(ra[i], rb[j], acc[i][j]);
        }
    }
    #pragma unroll
    for (int i = 0; i < 4; ++i) {
        int mm = m0 + ty*4 + i;
        #pragma unroll
        for (int j = 0; j < 4; ++j) {
            int n = n0 + tx*4 + j;
            out[(size_t)mm * CD + n] = acc[i][j] + bias[n];
        }
    }
}

// ---------------------------------------------------------------------------
extern "C" void kernel_launch(void* const* d_in, const int* in_sizes, int n_in,
                              void* d_out, int out_size) {
    const float* query = (const float*)d_in[0];
    const float* key_  = (const float*)d_in[1];
    const float* value = (const float*)d_in[2];
    const float* Wq = (const float*)d_in[3];
    const float* bq = (const float*)d_in[4];
    const float* Wk = (const float*)d_in[5];
    const float* bk = (const float*)d_in[6];
    const float* Wv = (const float*)d_in[7];
    const float* bv = (const float*)d_in[8];
    const float* Wo = (const float*)d_in[9];
    const float* bo = (const float*)d_in[10];
    const void*  mask = d_in[11];

    float* out = (float*)d_out;
    float *qp, *kp, *vp, *attn;
    cudaGetSymbolAddress((void**)&qp, g_q);
    cudaGetSymbolAddress((void**)&kp, g_k);
    cudaGetSymbolAddress((void**)&vp, g_v);
    if ((size_t)out_size >= (size_t)OUT_ELEMS + ATTN_ELEMS) {
        attn = out + OUT_ELEMS;   // output = concat(out, attn)
    } else {
        cudaGetSymbolAddress((void**)&attn, g_attn_fb);
    }

    detect_mask_kernel<<<1, 1>>>((const uint32_t*)mask);

    dim3 pg(CD/64, CM/64);
    proj_kernel<<<pg, 256>>>(query, Wq, bq, qp);
    proj_kernel<<<pg, 256>>>(key_,  Wk, bk, kp);
    proj_kernel<<<pg, 256>>>(value, Wv, bv, vp);

    qk_kernel<<<dim3(CS/64, CS/64, CBH), 256>>>(mask, attn);
    softmax_kernel<<<CBH*CS, 256>>>(attn);
    pv_kernel<<<dim3(CS/64, CBH), 256>>>(attn);
    outproj_kernel<<<dim3(CD/64, CM/64), 256>>>(Wo, bo, out);
}

// round 2
// speedup vs baseline: 1.2189x; 1.2189x over previous
#include <cuda_runtime.h>
#include <cstdint>

#define CB 2
#define CS 2048
#define CD 1024
#define CH 16
#define CHD 64
#define CBH (CB*CH)          // 32 batch-heads
#define CM (CB*CS)           // 4096 rows
#define OUT_ELEMS (CB*CS*CD)
#define ATTN_ELEMS ((size_t)CBH*CS*CS)

__device__ float g_q[CBH*CS*CHD];
__device__ float g_k[CBH*CS*CHD];
__device__ float g_v[CBH*CS*CHD];
__device__ float g_ctx[CBH*CS*CHD];
__device__ float g_attn_fb[(size_t)CBH*CS*CS];
__device__ int   g_mask_mode;

#define NEG_INF __int_as_float(0xff800000)

__global__ void detect_mask_kernel(const uint32_t* __restrict__ mask) {
    uint32_t w = mask[0];
    int mode = 0;
    if (w == 0x01010101u)      mode = 0;  // uint8 bool
    else if (w == 1u)          mode = 1;  // int32
    else if (w == 0x3F800000u) mode = 2;  // float32
    g_mask_mode = mode;
}

// ---------------------------------------------------------------------------
// Projection GEMM: [4096x1024] @ [1024x1024] + bias -> scatter to [B,H,S,HD]
// BM=BN=128, BK=8, 256 threads, 8x8 per thread, double-buffered smem.
// ---------------------------------------------------------------------------
__global__ void __launch_bounds__(256) proj_kernel(
    const float* __restrict__ A, const float* __restrict__ W,
    const float* __restrict__ bias, float* __restrict__ dst)
{
    __shared__ float As[2][8][132];
    __shared__ float Ws[2][8][128];
    const int tid = threadIdx.x;
    const int tx = tid & 15, ty = tid >> 4;
    const int m0 = blockIdx.y * 128, n0 = blockIdx.x * 128;
    const int arow = tid >> 1, acol = (tid & 1) * 4;
    const int wrow = tid >> 5, wc  = (tid & 31) * 4;

    const float* Aptr = A + (size_t)(m0 + arow) * CD + acol;
    const float* Wptr = W + (size_t)wrow * CD + n0 + wc;

    float4 a = *(const float4*)(Aptr);
    float4 w = *(const float4*)(Wptr);
    As[0][acol+0][arow]=a.x; As[0][acol+1][arow]=a.y;
    As[0][acol+2][arow]=a.z; As[0][acol+3][arow]=a.w;
    *(float4*)&Ws[0][wrow][wc] = w;
    __syncthreads();

    float acc[8][8] = {};
    int buf = 0;
    for (int k0 = 8; k0 <= CD; k0 += 8) {
        float4 na, nw;
        if (k0 < CD) {
            na = *(const float4*)(Aptr + k0);
            nw = *(const float4*)(Wptr + (size_t)k0 * CD);
        }
        #pragma unroll
        for (int k = 0; k < 8; ++k) {
            float ra[8], rb[8];
            *(float4*)(ra)   = *(const float4*)&As[buf][k][ty*4];
            *(float4*)(ra+4) = *(const float4*)&As[buf][k][64 + ty*4];
            *(float4*)(rb)   = *(const float4*)&Ws[buf][k][tx*4];
            *(float4*)(rb+4) = *(const float4*)&Ws[buf][k][64 + tx*4];
            #pragma unroll
            for (int i = 0; i < 8; ++i)
                #pragma unroll
                for (int j = 0; j < 8; ++j)
                    acc[i][j] = fmaf(ra[i], rb[j], acc[i][j]);
        }
        if (k0 < CD) {
            int nb = buf ^ 1;
            As[nb][acol+0][arow]=na.x; As[nb][acol+1][arow]=na.y;
            As[nb][acol+2][arow]=na.z; As[nb][acol+3][arow]=na.w;
            *(float4*)&Ws[nb][wrow][wc] = nw;
            __syncthreads();
            buf = nb;
        }
    }

    float4 b0 = *(const float4*)(bias + n0 + tx*4);
    float4 b1 = *(const float4*)(bias + n0 + 64 + tx*4);
    #pragma unroll
    for (int i = 0; i < 8; ++i) {
        int m = m0 + ((i < 4) ? (ty*4 + i) : (64 + ty*4 + i - 4));
        int b = m >> 11, s = m & (CS-1);
        #pragma unroll
        for (int jh = 0; jh < 2; ++jh) {
            int n = n0 + (jh ? (64 + tx*4) : (tx*4));
            int h = n >> 6, hd = n & 63;
            const float* bb = jh ? (const float*)&b1 : (const float*)&b0;
            float4 o;
            o.x = acc[i][jh*4+0] + bb[0];
            o.y = acc[i][jh*4+1] + bb[1];
            o.z = acc[i][jh*4+2] + bb[2];
            o.w = acc[i][jh*4+3] + bb[3];
            *(float4*)&dst[(((size_t)(b*CH + h)*CS) + s)*CHD + hd] = o;
        }
    }
}

// ---------------------------------------------------------------------------
// QK^T + scale + mask -> raw scores. BM=BN=128, K=64 (BK=16 double buffered).
// ---------------------------------------------------------------------------
__global__ void __launch_bounds__(256) qk_kernel(
    const void* __restrict__ maskp, float* __restrict__ scores)
{
    __shared__ float Qs[2][16][132];
    __shared__ float Ks[2][16][132];
    const int bh = blockIdx.z;
    const int q0 = blockIdx.y * 128, k0t = blockIdx.x * 128;
    const float* Qb = g_q + (size_t)bh * CS * CHD;
    const float* Kb = g_k + (size_t)bh * CS * CHD;
    const int tid = threadIdx.x, tx = tid & 15, ty = tid >> 4;
    const int lrow = tid >> 1, lcol = (tid & 1) * 8;

    const float* Qp = Qb + (size_t)(q0 + lrow) * CHD + lcol;
    const float* Kp = Kb + (size_t)(k0t + lrow) * CHD + lcol;

    {
        float4 qa = *(const float4*)(Qp);
        float4 qb2 = *(const float4*)(Qp + 4);
        float4 ka = *(const float4*)(Kp);
        float4 kb2 = *(const float4*)(Kp + 4);
        Qs[0][lcol+0][lrow]=qa.x; Qs[0][lcol+1][lrow]=qa.y; Qs[0][lcol+2][lrow]=qa.z; Qs[0][lcol+3][lrow]=qa.w;
        Qs[0][lcol+4][lrow]=qb2.x; Qs[0][lcol+5][lrow]=qb2.y; Qs[0][lcol+6][lrow]=qb2.z; Qs[0][lcol+7][lrow]=qb2.w;
        Ks[0][lcol+0][lrow]=ka.x; Ks[0][lcol+1][lrow]=ka.y; Ks[0][lcol+2][lrow]=ka.z; Ks[0][lcol+3][lrow]=ka.w;
        Ks[0][lcol+4][lrow]=kb2.x; Ks[0][lcol+5][lrow]=kb2.y; Ks[0][lcol+6][lrow]=kb2.z; Ks[0][lcol+7][lrow]=kb2.w;
    }
    __syncthreads();

    float acc[8][8] = {};
    int buf = 0;
    for (int d0 = 16; d0 <= CHD; d0 += 16) {
        float4 nq0, nq1, nk0, nk1;
        if (d0 < CHD) {
            nq0 = *(const float4*)(Qp + d0);
            nq1 = *(const float4*)(Qp + d0 + 4);
            nk0 = *(const float4*)(Kp + d0);
            nk1 = *(const float4*)(Kp + d0 + 4);
        }
        #pragma unroll
        for (int k = 0; k < 16; ++k) {
            float ra[8], rb[8];
            *(float4*)(ra)   = *(const float4*)&Qs[buf][k][ty*4];
            *(float4*)(ra+4) = *(const float4*)&Qs[buf][k][64 + ty*4];
            *(float4*)(rb)   = *(const float4*)&Ks[buf][k][tx*4];
            *(float4*)(rb+4) = *(const float4*)&Ks[buf][k][64 + tx*4];
            #pragma unroll
            for (int i = 0; i < 8; ++i)
                #pragma unroll
                for (int j = 0; j < 8; ++j)
                    acc[i][j] = fmaf(ra[i], rb[j], acc[i][j]);
        }
        if (d0 < CHD) {
            int nb = buf ^ 1;
            Qs[nb][lcol+0][lrow]=nq0.x; Qs[nb][lcol+1][lrow]=nq0.y; Qs[nb][lcol+2][lrow]=nq0.z; Qs[nb][lcol+3][lrow]=nq0.w;
            Qs[nb][lcol+4][lrow]=nq1.x; Qs[nb][lcol+5][lrow]=nq1.y; Qs[nb][lcol+6][lrow]=nq1.z; Qs[nb][lcol+7][lrow]=nq1.w;
            Ks[nb][lcol+0][lrow]=nk0.x; Ks[nb][lcol+1][lrow]=nk0.y; Ks[nb][lcol+2][lrow]=nk0.z; Ks[nb][lcol+3][lrow]=nk0.w;
            Ks[nb][lcol+4][lrow]=nk1.x; Ks[nb][lcol+5][lrow]=nk1.y; Ks[nb][lcol+6][lrow]=nk1.z; Ks[nb][lcol+7][lrow]=nk1.w;
            __syncthreads();
            buf = nb;
        }
    }

    const int mode = g_mask_mode;
    float* srow = scores + (size_t)bh * CS * CS;
    #pragma unroll
    for (int i = 0; i < 8; ++i) {
        int gq = q0 + ((i < 4) ? (ty*4 + i) : (64 + ty*4 + i - 4));
        size_t rowoff = (size_t)gq * CS;
        #pragma unroll
        for (int jh = 0; jh < 2; ++jh) {
            int gk = k0t + (jh ? (64 + tx*4) : (tx*4));
            bool kp[4];
            if (mode == 0) {
                uchar4 mm = *(const uchar4*)((const unsigned char*)maskp + rowoff + gk);
                kp[0] = mm.x; kp[1] = mm.y; kp[2] = mm.z; kp[3] = mm.w;
            } else if (mode == 1) {
                int4 mm = *(const int4*)((const int*)maskp + rowoff + gk);
                kp[0] = mm.x; kp[1] = mm.y; kp[2] = mm.z; kp[3] = mm.w;
            } else {
                float4 mm = *(const float4*)((const float*)maskp + rowoff + gk);
                kp[0] = mm.x != 0.f; kp[1] = mm.y != 0.f; kp[2] = mm.z != 0.f; kp[3] = mm.w != 0.f;
            }
            float4 o;
            o.x = kp[0] ? acc[i][jh*4+0] * 0.125f : NEG_INF;
            o.y = kp[1] ? acc[i][jh*4+1] * 0.125f : NEG_INF;
            o.z = kp[2] ? acc[i][jh*4+2] * 0.125f : NEG_INF;
            o.w = kp[3] ? acc[i][jh*4+3] * 0.125f : NEG_INF;
            *(float4*)(srow + rowoff + gk) = o;
        }
    }
}

// ---------------------------------------------------------------------------
// Row softmax, in place. One block per row.
// ---------------------------------------------------------------------------
__global__ void __launch_bounds__(256) softmax_kernel(float* __restrict__ attn)
{
    float* p = attn + (size_t)blockIdx.x * CS;
    const int tid = threadIdx.x;
    float v[8];
    #pragma unroll
    for (int i = 0; i < 8; ++i) v[i] = p[tid + i*256];

    float m = v[0];
    #pragma unroll
    for (int i = 1; i < 8; ++i) m = fmaxf(m, v[i]);
    __shared__ float redm[8], reds[8];
    #pragma unroll
    for (int o = 16; o > 0; o >>= 1) m = fmaxf(m, __shfl_xor_sync(0xffffffffu, m, o));
    if ((tid & 31) == 0) redm[tid >> 5] = m;
    __syncthreads();
    m = redm[0];
    #pragma unroll
    for (int i = 1; i < 8; ++i) m = fmaxf(m, redm[i]);

    float s = 0.f;
    #pragma unroll
    for (int i = 0; i < 8; ++i) { v[i] = __expf(v[i] - m); s += v[i]; }
    #pragma unroll
    for (int o = 16; o > 0; o >>= 1) s += __shfl_xor_sync(0xffffffffu, s, o);
    if ((tid & 31) == 0) reds[tid >> 5] = s;
    __syncthreads();
    s = 0.f;
    #pragma unroll
    for (int i = 0; i < 8; ++i) s += reds[i];
    float inv = 1.0f / s;
    #pragma unroll
    for (int i = 0; i < 8; ++i) p[tid + i*256] = v[i] * inv;
}

// ---------------------------------------------------------------------------
// PV: ctx = attn(2048x2048) @ V(2048x64). BM=128, BN=64, BK=16, 128 threads,
// 8x8 per thread, double buffered.
// ---------------------------------------------------------------------------
__global__ void __launch_bounds__(128) pv_kernel(const float* __restrict__ attn)
{
    __shared__ float As[2][16][132];
    __shared__ float Vs[2][16][68];
    const int bh = blockIdx.y, m0 = blockIdx.x * 128;
    const float* Ab = attn + (size_t)bh * CS * CS;
    const float* Vb = g_v + (size_t)bh * CS * CHD;
    const int tid = threadIdx.x, tx = tid & 7, ty = tid >> 3;
    const int vrow = tid >> 3, vc = (tid & 7) * 8;

    const float* Ap = Ab + (size_t)(m0 + tid) * CS;
    const float* Vp = Vb + (size_t)vrow * CHD + vc;

    {
        float4 a0 = *(const float4*)(Ap + 0);
        float4 a1 = *(const float4*)(Ap + 4);
        float4 a2 = *(const float4*)(Ap + 8);
        float4 a3 = *(const float4*)(Ap + 12);
        float4 v0 = *(const float4*)(Vp);
        float4 v1 = *(const float4*)(Vp + 4);
        As[0][ 0][tid]=a0.x; As[0][ 1][tid]=a0.y; As[0][ 2][tid]=a0.z; As[0][ 3][tid]=a0.w;
        As[0][ 4][tid]=a1.x; As[0][ 5][tid]=a1.y; As[0][ 6][tid]=a1.z; As[0][ 7][tid]=a1.w;
        As[0][ 8][tid]=a2.x; As[0][ 9][tid]=a2.y; As[0][10][tid]=a2.z; As[0][11][tid]=a2.w;
        As[0][12][tid]=a3.x; As[0][13][tid]=a3.y; As[0][14][tid]=a3.z; As[0][15][tid]=a3.w;
        *(float4*)&Vs[0][vrow][vc]   = v0;
        *(float4*)&Vs[0][vrow][vc+4] = v1;
    }
    __syncthreads();

    float acc[8][8] = {};
    int buf = 0;
    for (int k0 = 16; k0 <= CS; k0 += 16) {
        float4 na0, na1, na2, na3, nv0, nv1;
        if (k0 < CS) {
            na0 = *(const float4*)(Ap + k0 + 0);
            na1 = *(const float4*)(Ap + k0 + 4);
            na2 = *(const float4*)(Ap + k0 + 8);
            na3 = *(const float4*)(Ap + k0 + 12);
            nv0 = *(const float4*)(Vp + (size_t)k0 * CHD);
            nv1 = *(const float4*)(Vp + (size_t)k0 * CHD + 4);
        }
        #pragma unroll
        for (int k = 0; k < 16; ++k) {
            float ra[8], rb[8];
            *(float4*)(ra)   = *(const float4*)&As[buf][k][ty*4];
            *(float4*)(ra+4) = *(const float4*)&As[buf][k][64 + ty*4];
            *(float4*)(rb)   = *(const float4*)&Vs[buf][k][tx*4];
            *(float4*)(rb+4) = *(const float4*)&Vs[buf][k][32 + tx*4];
            #pragma unroll
            for (int i = 0; i < 8; ++i)
                #pragma unroll
                for (int j = 0; j < 8; ++j)
                    acc[i][j] = fmaf(ra[i], rb[j], acc[i][j]);
        }
        if (k0 < CS) {
            int nb = buf ^ 1;
            As[nb][ 0][tid]=na0.x; As[nb][ 1][tid]=na0.y; As[nb][ 2][tid]=na0.z; As[nb][ 3][tid]=na0.w;
            As[nb][ 4][tid]=na1.x; As[nb][ 5][tid]=na1.y; As[nb][ 6][tid]=na1.z; As[nb][ 7][tid]=na1.w;
            As[nb][ 8][tid]=na2.x; As[nb][ 9][tid]=na2.y; As[nb][10][tid]=na2.z; As[nb][11][tid]=na2.w;
            As[nb][12][tid]=na3.x; As[nb][13][tid]=na3.y; As[nb][14][tid]=na3.z; As[nb][15][tid]=na3.w;
            *(float4*)&Vs[nb][vrow][vc]   = nv0;
            *(float4*)&Vs[nb][vrow][vc+4] = nv1;
            __syncthreads();
            buf = nb;
        }
    }

    float* ctxb = g_ctx + (size_t)bh * CS * CHD;
    #pragma unroll
    for (int i = 0; i < 8; ++i) {
        int r = m0 + ((i < 4) ? (ty*4 + i) : (64 + ty*4 + i - 4));
        #pragma unroll
        for (int jh = 0; jh < 2; ++jh) {
            int c = (jh ? (32 + tx*4) : (tx*4));
            float4 o;
            o.x = acc[i][jh*4+0]; o.y = acc[i][jh*4+1];
            o.z = acc[i][jh*4+2]; o.w = acc[i][jh*4+3];
            *(float4*)&ctxb[(size_t)r * CHD + c] = o;
        }
    }
}

// ---------------------------------------------------------------------------
// Output projection with gather from [B,H,S,HD]. Same tiling as proj.
// ---------------------------------------------------------------------------
__global__ void __launch_bounds__(256) outproj_kernel(
    const float* __restrict__ W, const float* __restrict__ bias, float* __restrict__ out)
{
    __shared__ float As[2][8][132];
    __shared__ float Ws[2][8][128];
    const int tid = threadIdx.x;
    const int tx = tid & 15, ty = tid >> 4;
    const int m0 = blockIdx.y * 128, n0 = blockIdx.x * 128;
    const int arow = tid >> 1, acol = (tid & 1) * 4;
    const int wrow = tid >> 5, wc  = (tid & 31) * 4;

    const int m = m0 + arow;
    const int b = m >> 11, s = m & (CS-1);
    const float* ctxb = g_ctx + ((size_t)b*CH*CS + s) * CHD;
    const float* Wptr = W + (size_t)wrow * CD + n0 + wc;

    {
        int k = acol;
        float4 a = *(const float4*)(ctxb + (size_t)(k >> 6) * CS * CHD + (k & 63));
        float4 w = *(const float4*)(Wptr);
        As[0][acol+0][arow]=a.x; As[0][acol+1][arow]=a.y;
        As[0][acol+2][arow]=a.z; As[0][acol+3][arow]=a.w;
        *(float4*)&Ws[0][wrow][wc] = w;
    }
    __syncthreads();

    float acc[8][8] = {};
    int buf = 0;
    for (int k0 = 8; k0 <= CD; k0 += 8) {
        float4 na, nw;
        if (k0 < CD) {
            int k = k0 + acol;
            na = *(const float4*)(ctxb + (size_t)(k >> 6) * CS * CHD + (k & 63));
            nw = *(const float4*)(Wptr + (size_t)k0 * CD);
        }
        #pragma unroll
        for (int k = 0; k < 8; ++k) {
            float ra[8], rb[8];
            *(float4*)(ra)   = *(const float4*)&As[buf][k][ty*4];
            *(float4*)(ra+4) = *(const float4*)&As[buf][k][64 + ty*4];
            *(float4*)(rb)   = *(const float4*)&Ws[buf][k][tx*4];
            *(float4*)(rb+4) = *(const float4*)&Ws[buf][k][64 + tx*4];
            #pragma unroll
            for (int i = 0; i < 8; ++i)
                #pragma unroll
                for (int j = 0; j < 8; ++j)
                    acc[i][j] = fmaf(ra[i], rb[j], acc[i][j]);
        }
        if (k0 < CD) {
            int nb = buf ^ 1;
            As[nb][acol+0][arow]=na.x; As[nb][acol+1][arow]=na.y;
            As[nb][acol+2][arow]=na.z; As[nb][acol+3][arow]=na.w;
            *(float4*)&Ws[nb][wrow][wc] = nw;
            __syncthreads();
            buf = nb;
        }
    }

    float4 b0 = *(const float4*)(bias + n0 + tx*4);
    float4 b1 = *(const float4*)(bias + n0 + 64 + tx*4);
    #pragma unroll
    for (int i = 0; i < 8; ++i) {
        int mm = m0 + ((i < 4) ? (ty*4 + i) : (64 + ty*4 + i - 4));
        #pragma unroll
        for (int jh = 0; jh < 2; ++jh) {
            int n = n0 + (jh ? (64 + tx*4) : (tx*4));
            const float* bb = jh ? (const float*)&b1 : (const float*)&b0;
            float4 o;
            o.x = acc[i][jh*4+0] + bb[0];
            o.y = acc[i][jh*4+1] + bb[1];
            o.z = acc[i][jh*4+2] + bb[2];
            o.w = acc[i][jh*4+3] + bb[3];
            *(float4*)&out[(size_t)mm * CD + n] = o;
        }
    }
}

// ---------------------------------------------------------------------------
extern "C" void kernel_launch(void* const* d_in, const int* in_sizes, int n_in,
                              void* d_out, int out_size) {
    const float* query = (const float*)d_in[0];
    const float* key_  = (const float*)d_in[1];
    const float* value = (const float*)d_in[2];
    const float* Wq = (const float*)d_in[3];
    const float* bq = (const float*)d_in[4];
    const float* Wk = (const float*)d_in[5];
    const float* bk = (const float*)d_in[6];
    const float* Wv = (const float*)d_in[7];
    const float* bv = (const float*)d_in[8];
    const float* Wo = (const float*)d_in[9];
    const float* bo = (const float*)d_in[10];
    const void*  mask = d_in[11];

    float* out = (float*)d_out;
    float *qp, *kp, *vp, *attn;
    cudaGetSymbolAddress((void**)&qp, g_q);
    cudaGetSymbolAddress((void**)&kp, g_k);
    cudaGetSymbolAddress((void**)&vp, g_v);
    if ((size_t)out_size >= (size_t)OUT_ELEMS + ATTN_ELEMS) {
        attn = out + OUT_ELEMS;
    } else {
        cudaGetSymbolAddress((void**)&attn, g_attn_fb);
    }

    detect_mask_kernel<<<1, 1>>>((const uint32_t*)mask);

    dim3 pg(CD/128, CM/128);               // (8, 32)
    proj_kernel<<<pg, 256>>>(query, Wq, bq, qp);
    proj_kernel<<<pg, 256>>>(key_,  Wk, bk, kp);
    proj_kernel<<<pg, 256>>>(value, Wv, bv, vp);

    qk_kernel<<<dim3(CS/128, CS/128, CBH), 256>>>(mask, attn);   // (16,16,32)
    softmax_kernel<<<CBH*CS, 256>>>(attn);
    pv_kernel<<<dim3(CS/128, CBH), 128>>>(attn);                 // (16,32)
    outproj_kernel<<<dim3(CD/128, CM/128), 256>>>(Wo, bo, out);
}

// round 3
// speedup vs baseline: 1.6048x; 1.3166x over previous
#include <cuda_runtime.h>
#include <cstdint>

#define CB 2
#define CS 2048
#define CD 1024
#define CH 16
#define CHD 64
#define CBH (CB*CH)
#define CM (CB*CS)
#define OUT_ELEMS (CB*CS*CD)
#define ATTN_ELEMS ((size_t)CBH*CS*CS)

__device__ float g_q[CBH*CS*CHD];
__device__ float g_k[CBH*CS*CHD];
__device__ float g_v[CBH*CS*CHD];
__device__ float g_ctx[CBH*CS*CHD];
__device__ float g_attn_fb[(size_t)CBH*CS*CS];
__device__ int   g_mask_mode;

#define NEG_INF __int_as_float(0xff800000)

__global__ void detect_mask_kernel(const uint32_t* __restrict__ mask) {
    uint32_t w = mask[0];
    int mode = 0;
    if (w == 0x01010101u)      mode = 0;  // uint8 bool
    else if (w == 1u)          mode = 1;  // int32
    else if (w == 0x3F800000u) mode = 2;  // float32
    g_mask_mode = mode;
}

__device__ __forceinline__ uint32_t f2tf(float f) {
    uint32_t r;
    asm("cvt.rna.tf32.f32 %0, %1;" : "=r"(r) : "f"(f));
    return r;
}

__device__ __forceinline__ void mma8(float* c, const uint32_t* a, const uint32_t* b) {
    asm volatile(
        "mma.sync.aligned.m16n8k8.row.col.f32.tf32.tf32.f32 "
        "{%0,%1,%2,%3}, {%4,%5,%6,%7}, {%8,%9}, {%0,%1,%2,%3};"
        : "+f"(c[0]), "+f"(c[1]), "+f"(c[2]), "+f"(c[3])
        : "r"(a[0]), "r"(a[1]), "r"(a[2]), "r"(a[3]), "r"(b[0]), "r"(b[1]));
}

// ===========================================================================
// proj: C[4096x1024] = A @ W + bias, scatter to [B,H,S,HD].
// CTA 128x128, kchunk 16, 256 thr (8 warps of 64x32), tf32 mma.
// smem fragment-major: sA[buf][kstep][mtile8][lane*4+reg], sB[...][ntile16][lane*2+reg]
// ===========================================================================
__global__ void __launch_bounds__(256) proj_mma(
    const float* __restrict__ A, const float* __restrict__ W,
    const float* __restrict__ bias, float* __restrict__ dst)
{
    __shared__ uint32_t sA[2*2*8*128];
    __shared__ uint32_t sB[2*2*16*64];
    const int tid = threadIdx.x;
    const int warp = tid >> 5, lane = tid & 31;
    const int g = lane >> 2, tg = lane & 3;
    const int m0 = blockIdx.y * 128, n0 = blockIdx.x * 128;
    const int wm = (warp & 1) * 64, wn = (warp >> 1) * 32;

    const int ar_ = tid >> 1;            // A row within tile
    const int akst = tid & 1;            // A k-half (8 k each)
    const float* Ap = A + (size_t)(m0 + ar_) * CD + akst * 8;
    const int bk_ = tid >> 4;            // B k-row (0..15)
    const int bn_ = (tid & 15) * 8;      // B n base
    const float* Bp = W + (size_t)bk_ * CD + n0 + bn_;

    float4 fa0, fa1, fb0, fb1;
    fa0 = *(const float4*)(Ap);     fa1 = *(const float4*)(Ap + 4);
    fb0 = *(const float4*)(Bp);     fb1 = *(const float4*)(Bp + 4);

    auto commit = [&](int buf) {
        int abase = ((buf*2 + akst)*8 + (ar_ >> 4))*128;
        int l0 = 4*(ar_ & 7);
        int rb = (ar_ >> 3) & 1;
        sA[abase + (l0+0)*4 + rb]     = f2tf(fa0.x);
        sA[abase + (l0+1)*4 + rb]     = f2tf(fa0.y);
        sA[abase + (l0+2)*4 + rb]     = f2tf(fa0.z);
        sA[abase + (l0+3)*4 + rb]     = f2tf(fa0.w);
        sA[abase + (l0+0)*4 + rb+2]   = f2tf(fa1.x);
        sA[abase + (l0+1)*4 + rb+2]   = f2tf(fa1.y);
        sA[abase + (l0+2)*4 + rb+2]   = f2tf(fa1.z);
        sA[abase + (l0+3)*4 + rb+2]   = f2tf(fa1.w);
        int kstepb = bk_ >> 3, regb = (bk_ >> 2) & 1, kb3 = bk_ & 3;
        int bbase = ((buf*2 + kstepb)*16 + (bn_ >> 3))*64;
        const float* f0 = &fb0.x; const float* f1 = &fb1.x;
        #pragma unroll
        for (int j = 0; j < 4; ++j) {
            sB[bbase + (4*j + kb3)*2 + regb]      = f2tf(f0[j]);
            sB[bbase + (16 + 4*j + kb3)*2 + regb] = f2tf(f1[j]);
        }
    };
    commit(0);
    __syncthreads();

    float acc[4][4][4] = {};
    int buf = 0;
    for (int c = 1; c <= 64; ++c) {
        float4 na0, na1, nb0, nb1;
        const bool more = c < 64;
        if (more) {
            int kc = c * 16;
            na0 = *(const float4*)(Ap + kc); na1 = *(const float4*)(Ap + kc + 4);
            nb0 = *(const float4*)(Bp + (size_t)kc * CD);
            nb1 = *(const float4*)(Bp + (size_t)kc * CD + 4);
        }
        #pragma unroll
        for (int ks = 0; ks < 2; ++ks) {
            uint32_t ar4[4][4], br2[4][2];
            #pragma unroll
            for (int i = 0; i < 4; ++i)
                *(uint4*)ar4[i] = *(const uint4*)&sA[((buf*2+ks)*8 + (wm>>4) + i)*128 + lane*4];
            #pragma unroll
            for (int j = 0; j < 4; ++j)
                *(uint2*)br2[j] = *(const uint2*)&sB[((buf*2+ks)*16 + (wn>>3) + j)*64 + lane*2];
            #pragma unroll
            for (int i = 0; i < 4; ++i)
                #pragma unroll
                for (int j = 0; j < 4; ++j)
                    mma8(acc[i][j], ar4[i], br2[j]);
        }
        if (more) {
            fa0 = na0; fa1 = na1; fb0 = nb0; fb1 = nb1;
            commit(buf ^ 1);
            __syncthreads();
            buf ^= 1;
        }
    }

    #pragma unroll
    for (int i = 0; i < 4; ++i) {
        int r0 = m0 + wm + i*16 + g;
        int r1 = r0 + 8;
        int b0i = r0 >> 11, s0 = r0 & (CS-1);
        int b1i = r1 >> 11, s1 = r1 & (CS-1);
        #pragma unroll
        for (int j = 0; j < 4; ++j) {
            int col = n0 + wn + j*8 + 2*tg;
            int h = col >> 6, hd = col & 63;
            float2 bb = *(const float2*)(bias + col);
            float2 o0 = { acc[i][j][0] + bb.x, acc[i][j][1] + bb.y };
            float2 o1 = { acc[i][j][2] + bb.x, acc[i][j][3] + bb.y };
            *(float2*)&dst[((size_t)(b0i*CH + h)*CS + s0)*CHD + hd] = o0;
            *(float2*)&dst[((size_t)(b1i*CH + h)*CS + s1)*CHD + hd] = o1;
        }
    }
}

// ===========================================================================
// qk: scores = scale * Q @ K^T, masked. CTA 128x128, K=64 (4 chunks of 16).
// ===========================================================================
__global__ void __launch_bounds__(256) qk_mma(
    const void* __restrict__ maskp, float* __restrict__ scores)
{
    __shared__ uint32_t sA[2*2*8*128];
    __shared__ uint32_t sB[2*2*16*64];
    const int tid = threadIdx.x;
    const int warp = tid >> 5, lane = tid & 31;
    const int g = lane >> 2, tg = lane & 3;
    const int bh = blockIdx.z;
    const int q0 = blockIdx.y * 128, k0t = blockIdx.x * 128;
    const int wm = (warp & 1) * 64, wn = (warp >> 1) * 32;
    const float* Qb = g_q + (size_t)bh * CS * CHD;
    const float* Kb = g_k + (size_t)bh * CS * CHD;

    const int ar_ = tid >> 1, akst = tid & 1;
    const float* Ap = Qb + (size_t)(q0 + ar_) * CHD + akst * 8;
    const int bn_ = tid >> 1, bkst = tid & 1;   // B^T: row n of K, d-half
    const float* Bp = Kb + (size_t)(k0t + bn_) * CHD + bkst * 8;

    float4 fa0, fa1, fb0, fb1;
    fa0 = *(const float4*)(Ap);  fa1 = *(const float4*)(Ap + 4);
    fb0 = *(const float4*)(Bp);  fb1 = *(const float4*)(Bp + 4);

    auto commit = [&](int buf) {
        int abase = ((buf*2 + akst)*8 + (ar_ >> 4))*128;
        int l0 = 4*(ar_ & 7);
        int rb = (ar_ >> 3) & 1;
        sA[abase + (l0+0)*4 + rb]   = f2tf(fa0.x);
        sA[abase + (l0+1)*4 + rb]   = f2tf(fa0.y);
        sA[abase + (l0+2)*4 + rb]   = f2tf(fa0.z);
        sA[abase + (l0+3)*4 + rb]   = f2tf(fa0.w);
        sA[abase + (l0+0)*4 + rb+2] = f2tf(fa1.x);
        sA[abase + (l0+1)*4 + rb+2] = f2tf(fa1.y);
        sA[abase + (l0+2)*4 + rb+2] = f2tf(fa1.z);
        sA[abase + (l0+3)*4 + rb+2] = f2tf(fa1.w);
        // B^T: element (d, n): kstep = bkst, lane = 4*(n&7)+ (d&3)=j, reg = q
        int bbase = ((buf*2 + bkst)*16 + (bn_ >> 3))*64;
        int bl0 = 4*(bn_ & 7);
        const float* f0 = &fb0.x; const float* f1 = &fb1.x;
        #pragma unroll
        for (int j = 0; j < 4; ++j) {
            sB[bbase + (bl0 + j)*2 + 0] = f2tf(f0[j]);
            sB[bbase + (bl0 + j)*2 + 1] = f2tf(f1[j]);
        }
    };
    commit(0);
    __syncthreads();

    float acc[4][4][4] = {};
    int buf = 0;
    for (int c = 1; c <= 4; ++c) {
        float4 na0, na1, nb0, nb1;
        const bool more = c < 4;
        if (more) {
            int kc = c * 16;
            na0 = *(const float4*)(Ap + kc); na1 = *(const float4*)(Ap + kc + 4);
            nb0 = *(const float4*)(Bp + kc); nb1 = *(const float4*)(Bp + kc + 4);
        }
        #pragma unroll
        for (int ks = 0; ks < 2; ++ks) {
            uint32_t ar4[4][4], br2[4][2];
            #pragma unroll
            for (int i = 0; i < 4; ++i)
                *(uint4*)ar4[i] = *(const uint4*)&sA[((buf*2+ks)*8 + (wm>>4) + i)*128 + lane*4];
            #pragma unroll
            for (int j = 0; j < 4; ++j)
                *(uint2*)br2[j] = *(const uint2*)&sB[((buf*2+ks)*16 + (wn>>3) + j)*64 + lane*2];
            #pragma unroll
            for (int i = 0; i < 4; ++i)
                #pragma unroll
                for (int j = 0; j < 4; ++j)
                    mma8(acc[i][j], ar4[i], br2[j]);
        }
        if (more) {
            fa0 = na0; fa1 = na1; fb0 = nb0; fb1 = nb1;
            commit(buf ^ 1);
            __syncthreads();
            buf ^= 1;
        }
    }

    const int mode = g_mask_mode;
    float* srow = scores + (size_t)bh * CS * CS;
    #pragma unroll
    for (int i = 0; i < 4; ++i) {
        int r0 = q0 + wm + i*16 + g;
        int r1 = r0 + 8;
        #pragma unroll
        for (int j = 0; j < 4; ++j) {
            int col = k0t + wn + j*8 + 2*tg;
            size_t off0 = (size_t)r0 * CS + col;
            size_t off1 = (size_t)r1 * CS + col;
            bool k00, k01, k10, k11;
            if (mode == 0) {
                uchar2 a = *(const uchar2*)((const unsigned char*)maskp + off0);
                uchar2 b = *(const uchar2*)((const unsigned char*)maskp + off1);
                k00 = a.x; k01 = a.y; k10 = b.x; k11 = b.y;
            } else if (mode == 1) {
                int2 a = *(const int2*)((const int*)maskp + off0);
                int2 b = *(const int2*)((const int*)maskp + off1);
                k00 = a.x; k01 = a.y; k10 = b.x; k11 = b.y;
            } else {
                float2 a = *(const float2*)((const float*)maskp + off0);
                float2 b = *(const float2*)((const float*)maskp + off1);
                k00 = a.x != 0.f; k01 = a.y != 0.f; k10 = b.x != 0.f; k11 = b.y != 0.f;
            }
            float2 o0 = { k00 ? acc[i][j][0]*0.125f : NEG_INF,
                          k01 ? acc[i][j][1]*0.125f : NEG_INF };
            float2 o1 = { k10 ? acc[i][j][2]*0.125f : NEG_INF,
                          k11 ? acc[i][j][3]*0.125f : NEG_INF };
            *(float2*)(srow + off0) = o0;
            *(float2*)(srow + off1) = o1;
        }
    }
}

// ===========================================================================
// softmax (unchanged)
// ===========================================================================
__global__ void __launch_bounds__(256) softmax_kernel(float* __restrict__ attn)
{
    float* p = attn + (size_t)blockIdx.x * CS;
    const int tid = threadIdx.x;
    float v[8];
    #pragma unroll
    for (int i = 0; i < 8; ++i) v[i] = p[tid + i*256];
    float m = v[0];
    #pragma unroll
    for (int i = 1; i < 8; ++i) m = fmaxf(m, v[i]);
    __shared__ float redm[8], reds[8];
    #pragma unroll
    for (int o = 16; o > 0; o >>= 1) m = fmaxf(m, __shfl_xor_sync(0xffffffffu, m, o));
    if ((tid & 31) == 0) redm[tid >> 5] = m;
    __syncthreads();
    m = redm[0];
    #pragma unroll
    for (int i = 1; i < 8; ++i) m = fmaxf(m, redm[i]);
    float s = 0.f;
    #pragma unroll
    for (int i = 0; i < 8; ++i) { v[i] = __expf(v[i] - m); s += v[i]; }
    #pragma unroll
    for (int o = 16; o > 0; o >>= 1) s += __shfl_xor_sync(0xffffffffu, s, o);
    if ((tid & 31) == 0) reds[tid >> 5] = s;
    __syncthreads();
    s = 0.f;
    #pragma unroll
    for (int i = 0; i < 8; ++i) s += reds[i];
    float inv = 1.0f / s;
    #pragma unroll
    for (int i = 0; i < 8; ++i) p[tid + i*256] = v[i] * inv;
}

// ===========================================================================
// pv: ctx = attn(2048x2048) @ V(2048x64). CTA 256x64, kchunk 16, 256 thr,
// 8 warps of 64x32.
// ===========================================================================
__global__ void __launch_bounds__(256) pv_mma(const float* __restrict__ attn)
{
    __shared__ uint32_t sA[2*2*16*128];  // MT=16
    __shared__ uint32_t sB[2*2*8*64];    // NT=8
    const int tid = threadIdx.x;
    const int warp = tid >> 5, lane = tid & 31;
    const int g = lane >> 2, tg = lane & 3;
    const int bh = blockIdx.y, m0 = blockIdx.x * 256;
    const int wm = (warp & 3) * 64, wn = (warp >> 2) * 32;
    const float* Ab = attn + (size_t)bh * CS * CS;
    const float* Vb = g_v + (size_t)bh * CS * CHD;

    const float* Ap = Ab + (size_t)(m0 + tid) * CS;     // row tid, 16 k / chunk
    const int bk_ = tid >> 4, bn_ = (tid & 15) * 4;
    const float* Bp = Vb + (size_t)bk_ * CHD + bn_;

    float4 fa[4], fbv;
    #pragma unroll
    for (int q = 0; q < 4; ++q) fa[q] = *(const float4*)(Ap + q*4);
    fbv = *(const float4*)(Bp);

    auto commit = [&](int buf) {
        int mt = tid >> 4;
        int l0 = 4*(tid & 7);
        int rb = (tid >> 3) & 1;
        #pragma unroll
        for (int q = 0; q < 4; ++q) {
            int kstep = q >> 1;
            int reg = rb + 2*(q & 1);
            int base = ((buf*2 + kstep)*16 + mt)*128;
            const float* f = &fa[q].x;
            #pragma unroll
            for (int j = 0; j < 4; ++j)
                sA[base + (l0 + j)*4 + reg] = f2tf(f[j]);
        }
        int kstepb = bk_ >> 3, regb = (bk_ >> 2) & 1, kb3 = bk_ & 3;
        int bbase = ((buf*2 + kstepb)*8 + (bn_ >> 3))*64;
        int nl0 = bn_ & 7;
        const float* f = &fbv.x;
        #pragma unroll
        for (int j = 0; j < 4; ++j)
            sB[bbase + (4*(nl0 + j) + kb3)*2 + regb] = f2tf(f[j]);
    };
    commit(0);
    __syncthreads();

    float acc[4][4][4] = {};
    int buf = 0;
    for (int c = 1; c <= 128; ++c) {
        float4 na[4], nb;
        const bool more = c < 128;
        if (more) {
            int kc = c * 16;
            #pragma unroll
            for (int q = 0; q < 4; ++q) na[q] = *(const float4*)(Ap + kc + q*4);
            nb = *(const float4*)(Bp + (size_t)kc * CHD);
        }
        #pragma unroll
        for (int ks = 0; ks < 2; ++ks) {
            uint32_t ar4[4][4], br2[4][2];
            #pragma unroll
            for (int i = 0; i < 4; ++i)
                *(uint4*)ar4[i] = *(const uint4*)&sA[((buf*2+ks)*16 + (wm>>4) + i)*128 + lane*4];
            #pragma unroll
            for (int j = 0; j < 4; ++j)
                *(uint2*)br2[j] = *(const uint2*)&sB[((buf*2+ks)*8 + (wn>>3) + j)*64 + lane*2];
            #pragma unroll
            for (int i = 0; i < 4; ++i)
                #pragma unroll
                for (int j = 0; j < 4; ++j)
                    mma8(acc[i][j], ar4[i], br2[j]);
        }
        if (more) {
            #pragma unroll
            for (int q = 0; q < 4; ++q) fa[q] = na[q];
            fbv = nb;
            commit(buf ^ 1);
            __syncthreads();
            buf ^= 1;
        }
    }

    float* ctxb = g_ctx + (size_t)bh * CS * CHD;
    #pragma unroll
    for (int i = 0; i < 4; ++i) {
        int r0 = m0 + wm + i*16 + g;
        int r1 = r0 + 8;
        #pragma unroll
        for (int j = 0; j < 4; ++j) {
            int col = wn + j*8 + 2*tg;
            float2 o0 = { acc[i][j][0], acc[i][j][1] };
            float2 o1 = { acc[i][j][2], acc[i][j][3] };
            *(float2*)&ctxb[(size_t)r0 * CHD + col] = o0;
            *(float2*)&ctxb[(size_t)r1 * CHD + col] = o1;
        }
    }
}

// ===========================================================================
// outproj: out = ctx(gather [B,H,S,HD] -> [M,1024]) @ Wo + bo
// ===========================================================================
__global__ void __launch_bounds__(256) outproj_mma(
    const float* __restrict__ W, const float* __restrict__ bias, float* __restrict__ out)
{
    __shared__ uint32_t sA[2*2*8*128];
    __shared__ uint32_t sB[2*2*16*64];
    const int tid = threadIdx.x;
    const int warp = tid >> 5, lane = tid & 31;
    const int g = lane >> 2, tg = lane & 3;
    const int m0 = blockIdx.y * 128, n0 = blockIdx.x * 128;
    const int wm = (warp & 1) * 64, wn = (warp >> 1) * 32;

    const int ar_ = tid >> 1, akst = tid & 1;
    const int m = m0 + ar_;
    const int bidx = m >> 11, s = m & (CS-1);
    const float* ctxb = g_ctx + ((size_t)bidx*CH*CS + s) * CHD;  // + h*CS*CHD + hd
    const int bk_ = tid >> 4, bn_ = (tid & 15) * 8;
    const float* Bp = W + (size_t)bk_ * CD + n0 + bn_;

    auto fetchA = [&](int kc, float4& a0, float4& a1) {
        int kb = kc + akst * 8;
        const float* p = ctxb + (size_t)(kb >> 6) * CS * CHD + (kb & 63);
        a0 = *(const float4*)(p);
        a1 = *(const float4*)(p + 4);
    };

    float4 fa0, fa1, fb0, fb1;
    fetchA(0, fa0, fa1);
    fb0 = *(const float4*)(Bp); fb1 = *(const float4*)(Bp + 4);

    auto commit = [&](int buf) {
        int abase = ((buf*2 + akst)*8 + (ar_ >> 4))*128;
        int l0 = 4*(ar_ & 7);
        int rb = (ar_ >> 3) & 1;
        sA[abase + (l0+0)*4 + rb]   = f2tf(fa0.x);
        sA[abase + (l0+1)*4 + rb]   = f2tf(fa0.y);
        sA[abase + (l0+2)*4 + rb]   = f2tf(fa0.z);
        sA[abase + (l0+3)*4 + rb]   = f2tf(fa0.w);
        sA[abase + (l0+0)*4 + rb+2] = f2tf(fa1.x);
        sA[abase + (l0+1)*4 + rb+2] = f2tf(fa1.y);
        sA[abase + (l0+2)*4 + rb+2] = f2tf(fa1.z);
        sA[abase + (l0+3)*4 + rb+2] = f2tf(fa1.w);
        int kstepb = bk_ >> 3, regb = (bk_ >> 2) & 1, kb3 = bk_ & 3;
        int bbase = ((buf*2 + kstepb)*16 + (bn_ >> 3))*64;
        const float* f0 = &fb0.x; const float* f1 = &fb1.x;
        #pragma unroll
        for (int j = 0; j < 4; ++j) {
            sB[bbase + (4*j + kb3)*2 + regb]      = f2tf(f0[j]);
            sB[bbase + (16 + 4*j + kb3)*2 + regb] = f2tf(f1[j]);
        }
    };
    commit(0);
    __syncthreads();

    float acc[4][4][4] = {};
    int buf = 0;
    for (int c = 1; c <= 64; ++c) {
        float4 na0, na1, nb0, nb1;
        const bool more = c < 64;
        if (more) {
            int kc = c * 16;
            fetchA(kc, na0, na1);
            nb0 = *(const float4*)(Bp + (size_t)kc * CD);
            nb1 = *(const float4*)(Bp + (size_t)kc * CD + 4);
        }
        #pragma unroll
        for (int ks = 0; ks < 2; ++ks) {
            uint32_t ar4[4][4], br2[4][2];
            #pragma unroll
            for (int i = 0; i < 4; ++i)
                *(uint4*)ar4[i] = *(const uint4*)&sA[((buf*2+ks)*8 + (wm>>4) + i)*128 + lane*4];
            #pragma unroll
            for (int j = 0; j < 4; ++j)
                *(uint2*)br2[j] = *(const uint2*)&sB[((buf*2+ks)*16 + (wn>>3) + j)*64 + lane*2];
            #pragma unroll
            for (int i = 0; i < 4; ++i)
                #pragma unroll
                for (int j = 0; j < 4; ++j)
                    mma8(acc[i][j], ar4[i], br2[j]);
        }
        if (more) {
            fa0 = na0; fa1 = na1; fb0 = nb0; fb1 = nb1;
            commit(buf ^ 1);
            __syncthreads();
            buf ^= 1;
        }
    }

    #pragma unroll
    for (int i = 0; i < 4; ++i) {
        int r0 = m0 + wm + i*16 + g;
        int r1 = r0 + 8;
        #pragma unroll
        for (int j = 0; j < 4; ++j) {
            int col = n0 + wn + j*8 + 2*tg;
            float2 bb = *(const float2*)(bias + col);
            float2 o0 = { acc[i][j][0] + bb.x, acc[i][j][1] + bb.y };
            float2 o1 = { acc[i][j][2] + bb.x, acc[i][j][3] + bb.y };
            *(float2*)&out[(size_t)r0 * CD + col] = o0;
            *(float2*)&out[(size_t)r1 * CD + col] = o1;
        }
    }
}

// ===========================================================================
extern "C" void kernel_launch(void* const* d_in, const int* in_sizes, int n_in,
                              void* d_out, int out_size) {
    const float* query = (const float*)d_in[0];
    const float* key_  = (const float*)d_in[1];
    const float* value = (const float*)d_in[2];
    const float* Wq = (const float*)d_in[3];
    const float* bq = (const float*)d_in[4];
    const float* Wk = (const float*)d_in[5];
    const float* bk = (const float*)d_in[6];
    const float* Wv = (const float*)d_in[7];
    const float* bv = (const float*)d_in[8];
    const float* Wo = (const float*)d_in[9];
    const float* bo = (const float*)d_in[10];
    const void*  mask = d_in[11];

    float* out = (float*)d_out;
    float *qp, *kp, *vp, *attn;
    cudaGetSymbolAddress((void**)&qp, g_q);
    cudaGetSymbolAddress((void**)&kp, g_k);
    cudaGetSymbolAddress((void**)&vp, g_v);
    if ((size_t)out_size >= (size_t)OUT_ELEMS + ATTN_ELEMS) {
        attn = out + OUT_ELEMS;
    } else {
        cudaGetSymbolAddress((void**)&attn, g_attn_fb);
    }

    detect_mask_kernel<<<1, 1>>>((const uint32_t*)mask);

    dim3 pg(CD/128, CM/128);                       // (8, 32)
    proj_mma<<<pg, 256>>>(query, Wq, bq, qp);
    proj_mma<<<pg, 256>>>(key_,  Wk, bk, kp);
    proj_mma<<<pg, 256>>>(value, Wv, bv, vp);

    qk_mma<<<dim3(CS/128, CS/128, CBH), 256>>>(mask, attn);  // (16,16,32)
    softmax_kernel<<<CBH*CS, 256>>>(attn);
    pv_mma<<<dim3(CS/256, CBH), 256>>>(attn);                // (8,32)
    outproj_mma<<<dim3(CD/128, CM/128), 256>>>(Wo, bo, out);
}

// round 4
// speedup vs baseline: 1.8226x; 1.1357x over previous
#include <cuda_runtime.h>
#include <cstdint>

#define CB 2
#define CS 2048
#define CD 1024
#define CH 16
#define CHD 64
#define CBH (CB*CH)
#define CM (CB*CS)
#define OUT_ELEMS (CB*CS*CD)
#define ATTN_ELEMS ((size_t)CBH*CS*CS)

__device__ float g_q[CBH*CS*CHD];
__device__ float g_k[CBH*CS*CHD];
__device__ float g_v[CBH*CS*CHD];
__device__ float g_ctx[CBH*CS*CHD];
__device__ float g_attn_fb[(size_t)CBH*CS*CS];
__device__ int   g_mask_mode;

#define NEG_INF __int_as_float(0xff800000)

__global__ void detect_mask_kernel(const uint32_t* __restrict__ mask) {
    uint32_t w = mask[0];
    int mode = 0;
    if (w == 0x01010101u)      mode = 0;  // uint8 bool
    else if (w == 1u)          mode = 1;  // int32
    else if (w == 0x3F800000u) mode = 2;  // float32
    g_mask_mode = mode;
}

__device__ __forceinline__ uint32_t f2tf(float f) {
    uint32_t r;
    asm("cvt.rna.tf32.f32 %0, %1;" : "=r"(r) : "f"(f));
    return r;
}

__device__ __forceinline__ void mma8(float* c, const uint32_t* a, const uint32_t* b) {
    asm volatile(
        "mma.sync.aligned.m16n8k8.row.col.f32.tf32.tf32.f32 "
        "{%0,%1,%2,%3}, {%4,%5,%6,%7}, {%8,%9}, {%0,%1,%2,%3};"
        : "+f"(c[0]), "+f"(c[1]), "+f"(c[2]), "+f"(c[3])
        : "r"(a[0]), "r"(a[1]), "r"(a[2]), "r"(a[3]), "r"(b[0]), "r"(b[1]));
}

// ===========================================================================
// proj: C[4096x1024] = A @ W + bias, scatter to [B,H,S,HD].
// CTA 128x128, BK=16, 256 thr, 8 warps of 64x32. smem [k][m+pad]/[k][n+pad].
// ===========================================================================
__global__ void __launch_bounds__(256,2) proj_mma(
    const float* __restrict__ A, const float* __restrict__ W,
    const float* __restrict__ bias, float* __restrict__ dst)
{
    __shared__ uint32_t sA[2][16][132];
    __shared__ uint32_t sB[2][16][132];
    const int tid = threadIdx.x, warp = tid >> 5, lane = tid & 31;
    const int g = lane >> 2, tg = lane & 3;
    const int m0 = blockIdx.y * 128, n0 = blockIdx.x * 128;
    const int wm = (warp & 1) * 64, wn = (warp >> 1) * 32;

    const int ar_ = tid & 127, akst = tid >> 7;      // row, k-half(8)
    const float* Ap = A + (size_t)(m0 + ar_) * CD + akst * 8;
    const int bk_ = tid >> 4, bn_ = (tid & 15) * 8;  // B: 16 k-rows, 128 n
    const float* Bp = W + (size_t)bk_ * CD + n0 + bn_;

    float4 fa0, fa1, fb0, fb1;
    fa0 = *(const float4*)(Ap);  fa1 = *(const float4*)(Ap + 4);
    fb0 = *(const float4*)(Bp);  fb1 = *(const float4*)(Bp + 4);

    auto commit = [&](int buf) {
        const float* f0 = &fa0.x; const float* f1 = &fa1.x;
        #pragma unroll
        for (int j = 0; j < 4; ++j) {
            sA[buf][akst*8 + j][ar_]     = f2tf(f0[j]);
            sA[buf][akst*8 + 4 + j][ar_] = f2tf(f1[j]);
        }
        uint4 w0, w1;
        w0.x = f2tf(fb0.x); w0.y = f2tf(fb0.y); w0.z = f2tf(fb0.z); w0.w = f2tf(fb0.w);
        w1.x = f2tf(fb1.x); w1.y = f2tf(fb1.y); w1.z = f2tf(fb1.z); w1.w = f2tf(fb1.w);
        *(uint4*)&sB[buf][bk_][bn_]     = w0;
        *(uint4*)&sB[buf][bk_][bn_ + 4] = w1;
    };
    commit(0);
    __syncthreads();

    float acc[4][4][4] = {};
    int buf = 0;
    for (int c = 1; c <= 64; ++c) {
        float4 na0, na1, nb0, nb1;
        const bool more = c < 64;
        if (more) {
            int kc = c * 16;
            na0 = *(const float4*)(Ap + kc); na1 = *(const float4*)(Ap + kc + 4);
            nb0 = *(const float4*)(Bp + (size_t)kc * CD);
            nb1 = *(const float4*)(Bp + (size_t)kc * CD + 4);
        }
        #pragma unroll
        for (int ks = 0; ks < 2; ++ks) {
            uint32_t af[4][4], bf[4][2];
            #pragma unroll
            for (int i = 0; i < 4; ++i) {
                int m = wm + i*16 + g;
                af[i][0] = sA[buf][ks*8 + tg][m];
                af[i][1] = sA[buf][ks*8 + tg][m + 8];
                af[i][2] = sA[buf][ks*8 + tg + 4][m];
                af[i][3] = sA[buf][ks*8 + tg + 4][m + 8];
            }
            #pragma unroll
            for (int j = 0; j < 4; ++j) {
                int n = wn + j*8 + g;
                bf[j][0] = sB[buf][ks*8 + tg][n];
                bf[j][1] = sB[buf][ks*8 + tg + 4][n];
            }
            #pragma unroll
            for (int i = 0; i < 4; ++i)
                #pragma unroll
                for (int j = 0; j < 4; ++j)
                    mma8(acc[i][j], af[i], bf[j]);
        }
        if (more) {
            fa0 = na0; fa1 = na1; fb0 = nb0; fb1 = nb1;
            commit(buf ^ 1);
            __syncthreads();
            buf ^= 1;
        }
    }

    #pragma unroll
    for (int i = 0; i < 4; ++i) {
        int r0 = m0 + wm + i*16 + g;
        int r1 = r0 + 8;
        int b0i = r0 >> 11, s0 = r0 & (CS-1);
        int b1i = r1 >> 11, s1 = r1 & (CS-1);
        #pragma unroll
        for (int j = 0; j < 4; ++j) {
            int col = n0 + wn + j*8 + 2*tg;
            int h = col >> 6, hd = col & 63;
            float2 bb = *(const float2*)(bias + col);
            float2 o0 = { acc[i][j][0] + bb.x, acc[i][j][1] + bb.y };
            float2 o1 = { acc[i][j][2] + bb.x, acc[i][j][3] + bb.y };
            *(float2*)&dst[((size_t)(b0i*CH + h)*CS + s0)*CHD + hd] = o0;
            *(float2*)&dst[((size_t)(b1i*CH + h)*CS + s1)*CHD + hd] = o1;
        }
    }
}

// ===========================================================================
// qk: scores = scale * Q @ K^T, masked. CTA 128x128, K=64 (4 chunks of 16).
// ===========================================================================
__global__ void __launch_bounds__(256,2) qk_mma(
    const void* __restrict__ maskp, float* __restrict__ scores)
{
    __shared__ uint32_t sA[2][16][132];
    __shared__ uint32_t sB[2][16][132];
    const int tid = threadIdx.x, warp = tid >> 5, lane = tid & 31;
    const int g = lane >> 2, tg = lane & 3;
    const int bh = blockIdx.z;
    const int q0 = blockIdx.y * 128, k0t = blockIdx.x * 128;
    const int wm = (warp & 1) * 64, wn = (warp >> 1) * 32;
    const float* Qb = g_q + (size_t)bh * CS * CHD;
    const float* Kb = g_k + (size_t)bh * CS * CHD;

    const int ar_ = tid & 127, akst = tid >> 7;
    const float* Ap = Qb + (size_t)(q0 + ar_) * CHD + akst * 8;
    const float* Bp = Kb + (size_t)(k0t + ar_) * CHD + akst * 8;  // B^T rows

    float4 fa0, fa1, fb0, fb1;
    fa0 = *(const float4*)(Ap);  fa1 = *(const float4*)(Ap + 4);
    fb0 = *(const float4*)(Bp);  fb1 = *(const float4*)(Bp + 4);

    auto commit = [&](int buf) {
        const float* f0 = &fa0.x; const float* f1 = &fa1.x;
        const float* h0 = &fb0.x; const float* h1 = &fb1.x;
        #pragma unroll
        for (int j = 0; j < 4; ++j) {
            sA[buf][akst*8 + j][ar_]     = f2tf(f0[j]);
            sA[buf][akst*8 + 4 + j][ar_] = f2tf(f1[j]);
            sB[buf][akst*8 + j][ar_]     = f2tf(h0[j]);
            sB[buf][akst*8 + 4 + j][ar_] = f2tf(h1[j]);
        }
    };
    commit(0);
    __syncthreads();

    float acc[4][4][4] = {};
    int buf = 0;
    for (int c = 1; c <= 4; ++c) {
        float4 na0, na1, nb0, nb1;
        const bool more = c < 4;
        if (more) {
            int kc = c * 16;
            na0 = *(const float4*)(Ap + kc); na1 = *(const float4*)(Ap + kc + 4);
            nb0 = *(const float4*)(Bp + kc); nb1 = *(const float4*)(Bp + kc + 4);
        }
        #pragma unroll
        for (int ks = 0; ks < 2; ++ks) {
            uint32_t af[4][4], bf[4][2];
            #pragma unroll
            for (int i = 0; i < 4; ++i) {
                int m = wm + i*16 + g;
                af[i][0] = sA[buf][ks*8 + tg][m];
                af[i][1] = sA[buf][ks*8 + tg][m + 8];
                af[i][2] = sA[buf][ks*8 + tg + 4][m];
                af[i][3] = sA[buf][ks*8 + tg + 4][m + 8];
            }
            #pragma unroll
            for (int j = 0; j < 4; ++j) {
                int n = wn + j*8 + g;
                bf[j][0] = sB[buf][ks*8 + tg][n];
                bf[j][1] = sB[buf][ks*8 + tg + 4][n];
            }
            #pragma unroll
            for (int i = 0; i < 4; ++i)
                #pragma unroll
                for (int j = 0; j < 4; ++j)
                    mma8(acc[i][j], af[i], bf[j]);
        }
        if (more) {
            fa0 = na0; fa1 = na1; fb0 = nb0; fb1 = nb1;
            commit(buf ^ 1);
            __syncthreads();
            buf ^= 1;
        }
    }

    const int mode = g_mask_mode;
    float* srow = scores + (size_t)bh * CS * CS;
    #pragma unroll
    for (int i = 0; i < 4; ++i) {
        int r0 = q0 + wm + i*16 + g;
        int r1 = r0 + 8;
        #pragma unroll
        for (int j = 0; j < 4; ++j) {
            int col = k0t + wn + j*8 + 2*tg;
            size_t off0 = (size_t)r0 * CS + col;
            size_t off1 = (size_t)r1 * CS + col;
            bool k00, k01, k10, k11;
            if (mode == 0) {
                uchar2 a = *(const uchar2*)((const unsigned char*)maskp + off0);
                uchar2 b = *(const uchar2*)((const unsigned char*)maskp + off1);
                k00 = a.x; k01 = a.y; k10 = b.x; k11 = b.y;
            } else if (mode == 1) {
                int2 a = *(const int2*)((const int*)maskp + off0);
                int2 b = *(const int2*)((const int*)maskp + off1);
                k00 = a.x; k01 = a.y; k10 = b.x; k11 = b.y;
            } else {
                float2 a = *(const float2*)((const float*)maskp + off0);
                float2 b = *(const float2*)((const float*)maskp + off1);
                k00 = a.x != 0.f; k01 = a.y != 0.f; k10 = b.x != 0.f; k11 = b.y != 0.f;
            }
            float2 o0 = { k00 ? acc[i][j][0]*0.125f : NEG_INF,
                          k01 ? acc[i][j][1]*0.125f : NEG_INF };
            float2 o1 = { k10 ? acc[i][j][2]*0.125f : NEG_INF,
                          k11 ? acc[i][j][3]*0.125f : NEG_INF };
            *(float2*)(srow + off0) = o0;
            *(float2*)(srow + off1) = o1;
        }
    }
}

// ===========================================================================
// softmax (unchanged)
// ===========================================================================
__global__ void __launch_bounds__(256) softmax_kernel(float* __restrict__ attn)
{
    float* p = attn + (size_t)blockIdx.x * CS;
    const int tid = threadIdx.x;
    float v[8];
    #pragma unroll
    for (int i = 0; i < 8; ++i) v[i] = p[tid + i*256];
    float m = v[0];
    #pragma unroll
    for (int i = 1; i < 8; ++i) m = fmaxf(m, v[i]);
    __shared__ float redm[8], reds[8];
    #pragma unroll
    for (int o = 16; o > 0; o >>= 1) m = fmaxf(m, __shfl_xor_sync(0xffffffffu, m, o));
    if ((tid & 31) == 0) redm[tid >> 5] = m;
    __syncthreads();
    m = redm[0];
    #pragma unroll
    for (int i = 1; i < 8; ++i) m = fmaxf(m, redm[i]);
    float s = 0.f;
    #pragma unroll
    for (int i = 0; i < 8; ++i) { v[i] = __expf(v[i] - m); s += v[i]; }
    #pragma unroll
    for (int o = 16; o > 0; o >>= 1) s += __shfl_xor_sync(0xffffffffu, s, o);
    if ((tid & 31) == 0) reds[tid >> 5] = s;
    __syncthreads();
    s = 0.f;
    #pragma unroll
    for (int i = 0; i < 8; ++i) s += reds[i];
    float inv = 1.0f / s;
    #pragma unroll
    for (int i = 0; i < 8; ++i) p[tid + i*256] = v[i] * inv;
}

// ===========================================================================
// pv: ctx = attn(2048x2048) @ V(2048x64). CTA 256x64, BK=16, 256 thr,
// 8 warps of 64x32.
// ===========================================================================
__global__ void __launch_bounds__(256,2) pv_mma(const float* __restrict__ attn)
{
    __shared__ uint32_t sA[2][16][260];
    __shared__ uint32_t sB[2][16][68];
    const int tid = threadIdx.x, warp = tid >> 5, lane = tid & 31;
    const int g = lane >> 2, tg = lane & 3;
    const int bh = blockIdx.y, m0 = blockIdx.x * 256;
    const int wm = (warp & 3) * 64, wn = (warp >> 2) * 32;
    const float* Ab = attn + (size_t)bh * CS * CS;
    const float* Vb = g_v + (size_t)bh * CS * CHD;

    const float* Ap = Ab + (size_t)(m0 + tid) * CS;   // 1 row/thread, 16 k/chunk
    const int bk_ = tid >> 4, bn_ = (tid & 15) * 4;
    const float* Bp = Vb + (size_t)bk_ * CHD + bn_;

    float4 fa[4], fbv;
    #pragma unroll
    for (int q = 0; q < 4; ++q) fa[q] = *(const float4*)(Ap + q*4);
    fbv = *(const float4*)(Bp);

    auto commit = [&](int buf) {
        #pragma unroll
        for (int q = 0; q < 4; ++q) {
            const float* f = &fa[q].x;
            #pragma unroll
            for (int j = 0; j < 4; ++j)
                sA[buf][q*4 + j][tid] = f2tf(f[j]);
        }
        uint4 w;
        w.x = f2tf(fbv.x); w.y = f2tf(fbv.y); w.z = f2tf(fbv.z); w.w = f2tf(fbv.w);
        *(uint4*)&sB[buf][bk_][bn_] = w;
    };
    commit(0);
    __syncthreads();

    float acc[4][4][4] = {};
    int buf = 0;
    for (int c = 1; c <= 128; ++c) {
        float4 na[4], nb;
        const bool more = c < 128;
        if (more) {
            int kc = c * 16;
            #pragma unroll
            for (int q = 0; q < 4; ++q) na[q] = *(const float4*)(Ap + kc + q*4);
            nb = *(const float4*)(Bp + (size_t)kc * CHD);
        }
        #pragma unroll
        for (int ks = 0; ks < 2; ++ks) {
            uint32_t af[4][4], bf[4][2];
            #pragma unroll
            for (int i = 0; i < 4; ++i) {
                int m = wm + i*16 + g;
                af[i][0] = sA[buf][ks*8 + tg][m];
                af[i][1] = sA[buf][ks*8 + tg][m + 8];
                af[i][2] = sA[buf][ks*8 + tg + 4][m];
                af[i][3] = sA[buf][ks*8 + tg + 4][m + 8];
            }
            #pragma unroll
            for (int j = 0; j < 4; ++j) {
                int n = wn + j*8 + g;
                bf[j][0] = sB[buf][ks*8 + tg][n];
                bf[j][1] = sB[buf][ks*8 + tg + 4][n];
            }
            #pragma unroll
            for (int i = 0; i < 4; ++i)
                #pragma unroll
                for (int j = 0; j < 4; ++j)
                    mma8(acc[i][j], af[i], bf[j]);
        }
        if (more) {
            #pragma unroll
            for (int q = 0; q < 4; ++q) fa[q] = na[q];
            fbv = nb;
            commit(buf ^ 1);
            __syncthreads();
            buf ^= 1;
        }
    }

    float* ctxb = g_ctx + (size_t)bh * CS * CHD;
    #pragma unroll
    for (int i = 0; i < 4; ++i) {
        int r0 = m0 + wm + i*16 + g;
        int r1 = r0 + 8;
        #pragma unroll
        for (int j = 0; j < 4; ++j) {
            int col = wn + j*8 + 2*tg;
            float2 o0 = { acc[i][j][0], acc[i][j][1] };
            float2 o1 = { acc[i][j][2], acc[i][j][3] };
            *(float2*)&ctxb[(size_t)r0 * CHD + col] = o0;
            *(float2*)&ctxb[(size_t)r1 * CHD + col] = o1;
        }
    }
}

// ===========================================================================
// outproj: out = ctx(gather [B,H,S,HD] -> [M,1024]) @ Wo + bo
// ===========================================================================
__global__ void __launch_bounds__(256,2) outproj_mma(
    const float* __restrict__ W, const float* __restrict__ bias, float* __restrict__ out)
{
    __shared__ uint32_t sA[2][16][132];
    __shared__ uint32_t sB[2][16][132];
    const int tid = threadIdx.x, warp = tid >> 5, lane = tid & 31;
    const int g = lane >> 2, tg = lane & 3;
    const int m0 = blockIdx.y * 128, n0 = blockIdx.x * 128;
    const int wm = (warp & 1) * 64, wn = (warp >> 1) * 32;

    const int ar_ = tid & 127, akst = tid >> 7;
    const int m = m0 + ar_;
    const int bidx = m >> 11, s = m & (CS-1);
    const float* ctxb = g_ctx + ((size_t)bidx*CH*CS + s) * CHD;
    const int bk_ = tid >> 4, bn_ = (tid & 15) * 8;
    const float* Bp = W + (size_t)bk_ * CD + n0 + bn_;

    auto fetchA = [&](int kc, float4& a0, float4& a1) {
        int kb = kc + akst * 8;
        const float* p = ctxb + (size_t)(kb >> 6) * CS * CHD + (kb & 63);
        a0 = *(const float4*)(p);
        a1 = *(const float4*)(p + 4);
    };

    float4 fa0, fa1, fb0, fb1;
    fetchA(0, fa0, fa1);
    fb0 = *(const float4*)(Bp); fb1 = *(const float4*)(Bp + 4);

    auto commit = [&](int buf) {
        const float* f0 = &fa0.x; const float* f1 = &fa1.x;
        #pragma unroll
        for (int j = 0; j < 4; ++j) {
            sA[buf][akst*8 + j][ar_]     = f2tf(f0[j]);
            sA[buf][akst*8 + 4 + j][ar_] = f2tf(f1[j]);
        }
        uint4 w0, w1;
        w0.x = f2tf(fb0.x); w0.y = f2tf(fb0.y); w0.z = f2tf(fb0.z); w0.w = f2tf(fb0.w);
        w1.x = f2tf(fb1.x); w1.y = f2tf(fb1.y); w1.z = f2tf(fb1.z); w1.w = f2tf(fb1.w);
        *(uint4*)&sB[buf][bk_][bn_]     = w0;
        *(uint4*)&sB[buf][bk_][bn_ + 4] = w1;
    };
    commit(0);
    __syncthreads();

    float acc[4][4][4] = {};
    int buf = 0;
    for (int c = 1; c <= 64; ++c) {
        float4 na0, na1, nb0, nb1;
        const bool more = c < 64;
        if (more) {
            int kc = c * 16;
            fetchA(kc, na0, na1);
            nb0 = *(const float4*)(Bp + (size_t)kc * CD);
            nb1 = *(const float4*)(Bp + (size_t)kc * CD + 4);
        }
        #pragma unroll
        for (int ks = 0; ks < 2; ++ks) {
            uint32_t af[4][4], bf[4][2];
            #pragma unroll
            for (int i = 0; i < 4; ++i) {
                int mm = wm + i*16 + g;
                af[i][0] = sA[buf][ks*8 + tg][mm];
                af[i][1] = sA[buf][ks*8 + tg][mm + 8];
                af[i][2] = sA[buf][ks*8 + tg + 4][mm];
                af[i][3] = sA[buf][ks*8 + tg + 4][mm + 8];
            }
            #pragma unroll
            for (int j = 0; j < 4; ++j) {
                int n = wn + j*8 + g;
                bf[j][0] = sB[buf][ks*8 + tg][n];
                bf[j][1] = sB[buf][ks*8 + tg + 4][n];
            }
            #pragma unroll
            for (int i = 0; i < 4; ++i)
                #pragma unroll
                for (int j = 0; j < 4; ++j)
                    mma8(acc[i][j], af[i], bf[j]);
        }
        if (more) {
            fa0 = na0; fa1 = na1; fb0 = nb0; fb1 = nb1;
            commit(buf ^ 1);
            __syncthreads();
            buf ^= 1;
        }
    }

    #pragma unroll
    for (int i = 0; i < 4; ++i) {
        int r0 = m0 + wm + i*16 + g;
        int r1 = r0 + 8;
        #pragma unroll
        for (int j = 0; j < 4; ++j) {
            int col = n0 + wn + j*8 + 2*tg;
            float2 bb = *(const float2*)(bias + col);
            float2 o0 = { acc[i][j][0] + bb.x, acc[i][j][1] + bb.y };
            float2 o1 = { acc[i][j][2] + bb.x, acc[i][j][3] + bb.y };
            *(float2*)&out[(size_t)r0 * CD + col] = o0;
            *(float2*)&out[(size_t)r1 * CD + col] = o1;
        }
    }
}

// ===========================================================================
extern "C" void kernel_launch(void* const* d_in, const int* in_sizes, int n_in,
                              void* d_out, int out_size) {
    const float* query = (const float*)d_in[0];
    const float* key_  = (const float*)d_in[1];
    const float* value = (const float*)d_in[2];
    const float* Wq = (const float*)d_in[3];
    const float* bq = (const float*)d_in[4];
    const float* Wk = (const float*)d_in[5];
    const float* bk = (const float*)d_in[6];
    const float* Wv = (const float*)d_in[7];
    const float* bv = (const float*)d_in[8];
    const float* Wo = (const float*)d_in[9];
    const float* bo = (const float*)d_in[10];
    const void*  mask = d_in[11];

    float* out = (float*)d_out;
    float *qp, *kp, *vp, *attn;
    cudaGetSymbolAddress((void**)&qp, g_q);
    cudaGetSymbolAddress((void**)&kp, g_k);
    cudaGetSymbolAddress((void**)&vp, g_v);
    if ((size_t)out_size >= (size_t)OUT_ELEMS + ATTN_ELEMS) {
        attn = out + OUT_ELEMS;
    } else {
        cudaGetSymbolAddress((void**)&attn, g_attn_fb);
    }

    detect_mask_kernel<<<1, 1>>>((const uint32_t*)mask);

    dim3 pg(CD/128, CM/128);                       // (8, 32)
    proj_mma<<<pg, 256>>>(query, Wq, bq, qp);
    proj_mma<<<pg, 256>>>(key_,  Wk, bk, kp);
    proj_mma<<<pg, 256>>>(value, Wv, bv, vp);

    qk_mma<<<dim3(CS/128, CS/128, CBH), 256>>>(mask, attn);  // (16,16,32)
    softmax_kernel<<<CBH*CS, 256>>>(attn);
    pv_mma<<<dim3(CS/256, CBH), 256>>>(attn);                // (8,32)
    outproj_mma<<<dim3(CD/128, CM/128), 256>>>(Wo, bo, out);
}